// round 16
// baseline (speedup 1.0000x reference)
#include <cuda_runtime.h>
#include <cuda_bf16.h>
#include <cuda_fp16.h>
#include <math.h>
#include <cstdint>

#define N_NODES 100000
#define N_EDGES 800000
#define HCDIM   128
#define C_DIM   64
#define N_CLS   40
#define EPS_F   1e-16f

// weight scratch (bf16 hi/lo): W0[16384] W1[16384] W2[16384] W12[8192 = 64x128 padded]
#define WOFF_0  0
#define WOFF_1  16384
#define WOFF_2  32768
#define WOFF_12 49152
#define WTOT    57344

// ---------------- static device scratch ----------------
__device__ __align__(16) __nv_bfloat16 g_hb[(size_t)N_NODES * HCDIM];  // agg out (GEMM A)
__device__ __align__(16) __half2 g_pq [(size_t)N_NODES * HCDIM];       // (P,Q) per channel
__device__ __align__(16) float g_t[(size_t)N_NODES * C_DIM];           // head logits (padded)
__device__ __align__(16) __nv_bfloat16 g_wh[WTOT];
__device__ __align__(16) __nv_bfloat16 g_wl[WTOT];
__device__ float g_b12[64];
__device__ int g_deg[N_NODES];
__device__ int g_rowptr[N_NODES + 1];
__device__ int g_cursor[N_NODES];
__device__ int g_csrc[N_EDGES];

// ---------------- helpers ----------------
__device__ __forceinline__ uint32_t smem_to_u32(const void* p) {
    uint32_t a;
    asm("{ .reg .u64 t; cvta.to.shared.u64 t, %1; cvt.u32.u64 %0, t; }" : "=r"(a) : "l"(p));
    return a;
}
__device__ __forceinline__ void ldmatrix_x4(uint32_t* r, uint32_t addr) {
    asm volatile("ldmatrix.sync.aligned.m8n8.x4.shared.b16 {%0,%1,%2,%3}, [%4];"
        : "=r"(r[0]), "=r"(r[1]), "=r"(r[2]), "=r"(r[3]) : "r"(addr));
}
__device__ __forceinline__ void ldmatrix_x2(uint32_t* r, uint32_t addr) {
    asm volatile("ldmatrix.sync.aligned.m8n8.x2.shared.b16 {%0,%1}, [%2];"
        : "=r"(r[0]), "=r"(r[1]) : "r"(addr));
}
__device__ __forceinline__ void mma_bf16(float* c, const uint32_t* a, const uint32_t* b) {
    asm volatile("mma.sync.aligned.m16n8k16.row.col.f32.bf16.bf16.f32 "
        "{%0,%1,%2,%3}, {%4,%5,%6,%7}, {%8,%9}, {%0,%1,%2,%3};"
        : "+f"(c[0]), "+f"(c[1]), "+f"(c[2]), "+f"(c[3])
        : "r"(a[0]), "r"(a[1]), "r"(a[2]), "r"(a[3]), "r"(b[0]), "r"(b[1]));
}
__device__ __forceinline__ uint32_t pack_bf16(float a, float b) {
    __nv_bfloat162 p = __floats2bfloat162_rn(a, b);
    return *reinterpret_cast<uint32_t*>(&p);
}

// ---------------- CSR build + weight pre-conversion ----------------
__global__ void count_deg_convw_kernel(const int* __restrict__ dst,
                                       const float* __restrict__ W0,
                                       const float* __restrict__ W1,
                                       const float* __restrict__ W2) {
    int t = blockIdx.x * blockDim.x + threadIdx.x;
    if (t < N_EDGES) atomicAdd(&g_deg[dst[t]], 1);
    if (t < WOFF_12) {
        float v;
        if      (t < WOFF_1) v = W0[t - WOFF_0];
        else if (t < WOFF_2) v = W1[t - WOFF_1];
        else                 v = W2[t - WOFF_2];
        __nv_bfloat16 hi = __float2bfloat16_rn(v);
        g_wh[t] = hi;
        g_wl[t] = __float2bfloat16_rn(v - __bfloat162float(hi));
    }
}

// single-block chunked exclusive scan; re-zeroes g_deg for the next replay
__global__ void scan_kernel() {
    __shared__ int warp_sums[32];
    __shared__ int sCarry;
    const int tid  = threadIdx.x;       // 1024
    const int lane = tid & 31;
    const int wid  = tid >> 5;
    if (tid == 0) sCarry = 0;
    __syncthreads();
    for (int base = 0; base < N_NODES; base += 1024) {
        int idx = base + tid;
        int v = (idx < N_NODES) ? g_deg[idx] : 0;
        if (idx < N_NODES) g_deg[idx] = 0;
        int incl = v;
        #pragma unroll
        for (int d = 1; d < 32; d <<= 1) {
            int t = __shfl_up_sync(0xffffffffu, incl, d);
            if (lane >= d) incl += t;
        }
        if (lane == 31) warp_sums[wid] = incl;
        __syncthreads();
        if (wid == 0) {
            int s = warp_sums[lane];
            #pragma unroll
            for (int d = 1; d < 32; d <<= 1) {
                int t = __shfl_up_sync(0xffffffffu, s, d);
                if (lane >= d) s += t;
            }
            warp_sums[lane] = s;
        }
        __syncthreads();
        int carry = sCarry;
        int woff  = (wid > 0) ? warp_sums[wid - 1] : 0;
        int excl  = carry + woff + incl - v;
        if (idx < N_NODES) { g_rowptr[idx] = excl; g_cursor[idx] = excl; }
        __syncthreads();
        if (tid == 0) sCarry = carry + warp_sums[31];
        __syncthreads();
    }
    if (tid == 0) g_rowptr[N_NODES] = N_EDGES;
}

__global__ void scatter_kernel(const int* __restrict__ src, const int* __restrict__ dst) {
    int e = blockIdx.x * blockDim.x + threadIdx.x;
    if (e < N_EDGES) {
        int d   = dst[e];
        int pos = atomicAdd(&g_cursor[d], 1);
        g_csrc[pos] = src[e];
    }
}

// ---------------- head weight fold: W12 = Wp2 @ Wp1 [40,128] padded to 64 ----------------
__global__ void w12_prep_kernel(const float* __restrict__ Wp1, const float* __restrict__ bp1,
                                const float* __restrict__ Wp2, const float* __restrict__ bp2) {
    __shared__ float wp2s[N_CLS * C_DIM];
    const int tid = threadIdx.x;             // 256
    for (int i = tid; i < N_CLS * C_DIM; i += 256) wp2s[i] = Wp2[i];
    __syncthreads();
    for (int idx = tid; idx < 64 * 128; idx += 256) {
        int o = idx >> 7, k = idx & 127;
        float v = 0.f;
        if (o < N_CLS) {
            #pragma unroll 8
            for (int c = 0; c < C_DIM; c++)
                v += wp2s[o * C_DIM + c] * Wp1[c * 128 + k];
        }
        __nv_bfloat16 hi = __float2bfloat16_rn(v);
        g_wh[WOFF_12 + idx] = hi;
        g_wl[WOFF_12 + idx] = __float2bfloat16_rn(v - __bfloat162float(hi));
    }
    if (tid < 64) {
        float b = 0.f;
        if (tid < N_CLS) {
            for (int c = 0; c < C_DIM; c++) b += wp2s[tid * C_DIM + c] * bp1[c];
            b += bp2[tid];
        }
        g_b12[tid] = b;
    }
}

// ---------------- HMMA 2-term GEMM, BM=64 BN=64, warp tile 32x16 -----------------------
// A_FP32: A from fp32 x (convert to bf16-hi in stage). else A = g_hb (bf16).
// PQ_MODE: write half2(P,Q) to g_pq. else write fp32 logits to Out.
template <bool A_FP32, bool PQ_MODE>
__global__ void __launch_bounds__(256, 4) hmma_gemm2(
    const float* __restrict__ Afp,
    const __nv_bfloat16* __restrict__ whBase, const __nv_bfloat16* __restrict__ wlBase,
    const float* __restrict__ bias, const float* __restrict__ al,
    float* __restrict__ Out)
{
    constexpr int LD = 136;
    constexpr int CW = 16;
    constexpr int NT = 2;
    extern __shared__ char smem[];
    const uint32_t su = smem_to_u32(smem);
    const uint32_t OFF_A  = 0;
    const uint32_t OFF_BH = 64 * LD * 2;
    const uint32_t OFF_BL = OFF_BH + 64 * LD * 2;

    const int tid  = threadIdx.x;
    const int warp = tid >> 5;
    const int lane = tid & 31;
    const int warp_r = warp & 1;
    const int warp_c = warp >> 1;
    const int rowBase = blockIdx.x * 64;
    const int colBase = blockIdx.y * 64;
    const __nv_bfloat16* wh = whBase + (size_t)colBase * 128;
    const __nv_bfloat16* wl = wlBase + (size_t)colBase * 128;

    // ---- stage A ----
    if (A_FP32) {
        #pragma unroll
        for (int it = 0; it < 8; it++) {
            int i = tid + it * 256;           // 64*32 float4 slots
            int r = i >> 5, c = (i & 31) * 4;
            int grow = rowBase + r;
            float4 v = make_float4(0.f, 0.f, 0.f, 0.f);
            if (grow < N_NODES) v = *(const float4*)(Afp + (size_t)grow * 128 + c);
            uint2 hi = make_uint2(pack_bf16(v.x, v.y), pack_bf16(v.z, v.w));
            *(uint2*)(smem + OFF_A + ((size_t)r * LD + c) * 2) = hi;
        }
    } else {
        #pragma unroll
        for (int it = 0; it < 4; it++) {
            int i = tid + it * 256;           // 64*16 uint4 slots
            int r = i >> 4, c = (i & 15) * 8;
            int grow = rowBase + r;
            uint4 v = make_uint4(0u, 0u, 0u, 0u);
            if (grow < N_NODES) v = *(const uint4*)(g_hb + (size_t)grow * 128 + c);
            *(uint4*)(smem + OFF_A + ((size_t)r * LD + c) * 2) = v;
        }
    }
    // ---- stage B ----
    #pragma unroll
    for (int it = 0; it < 4; it++) {
        int i = tid + it * 256;
        int r = i >> 4, c = (i & 15) * 8;
        uint4 vh = *(const uint4*)(wh + (size_t)r * 128 + c);
        uint4 vl = *(const uint4*)(wl + (size_t)r * 128 + c);
        *(uint4*)(smem + OFF_BH + ((size_t)r * LD + c) * 2) = vh;
        *(uint4*)(smem + OFF_BL + ((size_t)r * LD + c) * 2) = vl;
    }
    __syncthreads();

    float acc[2][NT][4];
    #pragma unroll
    for (int s = 0; s < 2; s++)
        #pragma unroll
        for (int n = 0; n < NT; n++)
            #pragma unroll
            for (int j = 0; j < 4; j++) acc[s][n][j] = 0.f;

    uint32_t a_off[2];
    #pragma unroll
    for (int s = 0; s < 2; s++)
        a_off[s] = (uint32_t)(((warp_r * 32 + s * 16 + (lane & 7) + ((lane >> 3) & 1) * 8) * LD
                               + ((lane >> 4) * 8)) * 2);
    const uint32_t b_lane_off =
        (uint32_t)(((warp_c * CW + (lane & 7)) * LD + ((lane >> 3) & 1) * 8) * 2);

    #pragma unroll
    for (int k0 = 0; k0 < 128; k0 += 16) {
        uint32_t a0[4], a1[4];
        ldmatrix_x4(a0, su + OFF_A + a_off[0] + k0 * 2);
        ldmatrix_x4(a1, su + OFF_A + a_off[1] + k0 * 2);
        #pragma unroll
        for (int n = 0; n < NT; n++) {
            uint32_t bh[2], bl[2];
            uint32_t boff = b_lane_off + (uint32_t)(n * 8 * LD * 2) + k0 * 2;
            ldmatrix_x2(bh, su + OFF_BH + boff);
            ldmatrix_x2(bl, su + OFF_BL + boff);
            mma_bf16(acc[0][n], a0, bh);
            mma_bf16(acc[0][n], a0, bl);
            mma_bf16(acc[1][n], a1, bh);
            mma_bf16(acc[1][n], a1, bl);
        }
    }

    #pragma unroll
    for (int s = 0; s < 2; s++) {
        const int r0 = rowBase + warp_r * 32 + s * 16 + (lane >> 2);
        const int r1 = r0 + 8;
        #pragma unroll
        for (int n = 0; n < NT; n++) {
            const int col = colBase + warp_c * CW + n * 8 + (lane & 3) * 2;
            const float bx = bias[col], by = bias[col + 1];
            if (PQ_MODE) {
                const float a0 = al[col], a1 = al[col + 1];
                if (r0 < N_NODES) {
                    float h0v = acc[s][n][0] + bx, h1v = acc[s][n][1] + by;
                    float P0 = __expf(a0 * h0v), P1 = __expf(a1 * h1v);
                    __half2 x0 = __floats2half2_rn(P0, P0 * h0v);
                    __half2 x1 = __floats2half2_rn(P1, P1 * h1v);
                    uint2 u; u.x = *(uint32_t*)&x0; u.y = *(uint32_t*)&x1;
                    *(uint2*)(g_pq + (size_t)r0 * 128 + col) = u;
                }
                if (r1 < N_NODES) {
                    float h0v = acc[s][n][2] + bx, h1v = acc[s][n][3] + by;
                    float P0 = __expf(a0 * h0v), P1 = __expf(a1 * h1v);
                    __half2 x0 = __floats2half2_rn(P0, P0 * h0v);
                    __half2 x1 = __floats2half2_rn(P1, P1 * h1v);
                    uint2 u; u.x = *(uint32_t*)&x0; u.y = *(uint32_t*)&x1;
                    *(uint2*)(g_pq + (size_t)r1 * 128 + col) = u;
                }
            } else {
                if (r0 < N_NODES)
                    *(float2*)(Out + (size_t)r0 * 64 + col) =
                        make_float2(acc[s][n][0] + bx, acc[s][n][1] + by);
                if (r1 < N_NODES)
                    *(float2*)(Out + (size_t)r1 * 64 + col) =
                        make_float2(acc[s][n][2] + bx, acc[s][n][3] + by);
            }
        }
    }
}

// ---------------- aggregation: warp/node, gather half2(P,Q), write bf16 h ----------------
__global__ void gat_agg_sum() {
    const int node = blockIdx.x * (blockDim.x >> 5) + (threadIdx.x >> 5);
    if (node >= N_NODES) return;
    const int lane = threadIdx.x & 31;
    const int beg = g_rowptr[node];
    const int end = g_rowptr[node + 1];

    float S0=0.f,S1=0.f,S2=0.f,S3=0.f;
    float A0=0.f,A1=0.f,A2=0.f,A3=0.f;

    const uint4* __restrict__ pq = (const uint4*)g_pq;
    #define ACCUM(v) do { \
        __half2 p0 = *(__half2*)&(v).x, p1 = *(__half2*)&(v).y; \
        __half2 p2 = *(__half2*)&(v).z, p3 = *(__half2*)&(v).w; \
        float2 f0 = __half22float2(p0), f1 = __half22float2(p1); \
        float2 f2 = __half22float2(p2), f3 = __half22float2(p3); \
        S0 += f0.x; A0 += f0.y;  S1 += f1.x; A1 += f1.y; \
        S2 += f2.x; A2 += f2.y;  S3 += f3.x; A3 += f3.y; \
    } while (0)

    int e = beg;
    for (; e + 8 <= end; e += 8) {
        int s0 = __ldg(&g_csrc[e + 0]);
        int s1 = __ldg(&g_csrc[e + 1]);
        int s2 = __ldg(&g_csrc[e + 2]);
        int s3 = __ldg(&g_csrc[e + 3]);
        int s4 = __ldg(&g_csrc[e + 4]);
        int s5 = __ldg(&g_csrc[e + 5]);
        int s6 = __ldg(&g_csrc[e + 6]);
        int s7 = __ldg(&g_csrc[e + 7]);
        uint4 v0 = pq[(size_t)s0 * 32 + lane];
        uint4 v1 = pq[(size_t)s1 * 32 + lane];
        uint4 v2 = pq[(size_t)s2 * 32 + lane];
        uint4 v3 = pq[(size_t)s3 * 32 + lane];
        uint4 v4 = pq[(size_t)s4 * 32 + lane];
        uint4 v5 = pq[(size_t)s5 * 32 + lane];
        uint4 v6 = pq[(size_t)s6 * 32 + lane];
        uint4 v7 = pq[(size_t)s7 * 32 + lane];
        ACCUM(v0); ACCUM(v1); ACCUM(v2); ACCUM(v3);
        ACCUM(v4); ACCUM(v5); ACCUM(v6); ACCUM(v7);
    }
    for (; e + 2 <= end; e += 2) {
        int s0 = __ldg(&g_csrc[e + 0]);
        int s1 = __ldg(&g_csrc[e + 1]);
        uint4 v0 = pq[(size_t)s0 * 32 + lane];
        uint4 v1 = pq[(size_t)s1 * 32 + lane];
        ACCUM(v0); ACCUM(v1);
    }
    for (; e < end; e++) {
        int s = __ldg(&g_csrc[e]);
        uint4 v = pq[(size_t)s * 32 + lane];
        ACCUM(v);
    }
    #undef ACCUM

    float ox = fmaxf(A0 / (S0 + EPS_F), 0.f);
    float oy = fmaxf(A1 / (S1 + EPS_F), 0.f);
    float oz = fmaxf(A2 / (S2 + EPS_F), 0.f);
    float ow = fmaxf(A3 / (S3 + EPS_F), 0.f);
    uint2 u;
    u.x = pack_bf16(ox, oy);
    u.y = pack_bf16(oz, ow);
    *(uint2*)(g_hb + (size_t)node * HCDIM + lane * 4) = u;
}

// ---------------- log_softmax over 40 classes (reads padded [N,64] logits) ------------
__global__ void logsoftmax_kernel(float* __restrict__ out) {
    const int node = blockIdx.x * blockDim.x + threadIdx.x;
    if (node >= N_NODES) return;
    const float* row = g_t + (size_t)node * 64;
    float l[N_CLS];
    #pragma unroll
    for (int j = 0; j < N_CLS; j += 4) {
        float4 v = *(const float4*)(row + j);
        l[j] = v.x; l[j+1] = v.y; l[j+2] = v.z; l[j+3] = v.w;
    }
    float m = l[0];
    #pragma unroll
    for (int j = 1; j < N_CLS; j++) m = fmaxf(m, l[j]);
    float se = 0.f;
    #pragma unroll
    for (int j = 0; j < N_CLS; j++) se += __expf(l[j] - m);
    float lse = m + __logf(se);
    float* orow = out + (size_t)node * N_CLS;
    #pragma unroll
    for (int j = 0; j < N_CLS; j += 4) {
        float4 v = make_float4(l[j] - lse, l[j+1] - lse, l[j+2] - lse, l[j+3] - lse);
        *(float4*)(orow + j) = v;
    }
}

// ---------------- launch ----------------
extern "C" void kernel_launch(void* const* d_in, const int* in_sizes, int n_in,
                              void* d_out, int out_size) {
    const float* x   = (const float*)d_in[0];
    const int*   ei  = (const int*)  d_in[1];
    const float* W0  = (const float*)d_in[2];
    const float* b0  = (const float*)d_in[3];
    const float* al0 = (const float*)d_in[4];
    const float* W1  = (const float*)d_in[6];
    const float* b1  = (const float*)d_in[7];
    const float* al1 = (const float*)d_in[8];
    const float* W2  = (const float*)d_in[10];
    const float* b2  = (const float*)d_in[11];
    const float* al2 = (const float*)d_in[12];
    const float* Wp1 = (const float*)d_in[14];
    const float* bp1 = (const float*)d_in[15];
    const float* Wp2 = (const float*)d_in[16];
    const float* bp2 = (const float*)d_in[17];
    float* out = (float*)d_out;

    const int* srcv = ei;
    const int* dstv = ei + N_EDGES;

    float *tb, *b12;
    __nv_bfloat16 *wh, *wl;
    cudaGetSymbolAddress((void**)&tb, g_t);
    cudaGetSymbolAddress((void**)&wh, g_wh);
    cudaGetSymbolAddress((void**)&wl, g_wl);
    cudaGetSymbolAddress((void**)&b12, g_b12);

    constexpr int LD = 136;
    const int SMEM2 = (64 * LD + 2 * 64 * LD) * 2;          // 52224
    cudaFuncSetAttribute((const void*)hmma_gemm2<true, true>,
                         cudaFuncAttributeMaxDynamicSharedMemorySize, SMEM2);
    cudaFuncSetAttribute((const void*)hmma_gemm2<false, true>,
                         cudaFuncAttributeMaxDynamicSharedMemorySize, SMEM2);
    cudaFuncSetAttribute((const void*)hmma_gemm2<false, false>,
                         cudaFuncAttributeMaxDynamicSharedMemorySize, SMEM2);

    // CSR + weight conversion
    count_deg_convw_kernel<<<(N_EDGES + 255) / 256, 256>>>(dstv, W0, W1, W2);
    scan_kernel<<<1, 1024>>>();
    scatter_kernel<<<(N_EDGES + 255) / 256, 256>>>(srcv, dstv);

    const dim3 g2((N_NODES + 63) / 64, 2);
    const dim3 g1((N_NODES + 63) / 64, 1);
    const int aggGrid = (N_NODES + 7) / 8;

    // layer 0 (launch #4 -> ncu target)
    hmma_gemm2<true, true><<<g2, 256, SMEM2>>>(x, wh + WOFF_0, wl + WOFF_0, b0, al0, nullptr);
    w12_prep_kernel<<<1, 256>>>(Wp1, bp1, Wp2, bp2);
    gat_agg_sum<<<aggGrid, 256>>>();
    // layer 1
    hmma_gemm2<false, true><<<g2, 256, SMEM2>>>(nullptr, wh + WOFF_1, wl + WOFF_1, b1, al1, nullptr);
    gat_agg_sum<<<aggGrid, 256>>>();
    // layer 2
    hmma_gemm2<false, true><<<g2, 256, SMEM2>>>(nullptr, wh + WOFF_2, wl + WOFF_2, b2, al2, nullptr);
    gat_agg_sum<<<aggGrid, 256>>>();
    // head: fused (Wp2@Wp1) GEMM -> padded logits, then log_softmax
    hmma_gemm2<false, false><<<g1, 256, SMEM2>>>(nullptr, wh + WOFF_12, wl + WOFF_12, b12, nullptr, tb);
    logsoftmax_kernel<<<(N_NODES + 255) / 256, 256>>>(out);
}

// round 17
// speedup vs baseline: 1.0229x; 1.0229x over previous
#include <cuda_runtime.h>
#include <cuda_bf16.h>
#include <cuda_fp16.h>
#include <math.h>
#include <cstdint>

#define N_NODES 100000
#define N_EDGES 800000
#define HCDIM   128
#define C_DIM   64
#define N_CLS   40
#define EPS_F   1e-16f

// weight scratch (bf16 hi/lo): W0[16384] W1[16384] W2[16384] W12[8192 = 64x128 padded]
#define WOFF_0  0
#define WOFF_1  16384
#define WOFF_2  32768
#define WOFF_12 49152
#define WTOT    57344

// ---------------- static device scratch ----------------
__device__ __align__(16) __nv_bfloat16 g_hb[(size_t)N_NODES * HCDIM];  // agg out (GEMM A)
__device__ __align__(16) __half2 g_pq [(size_t)N_NODES * HCDIM];       // (P,Q) per channel
__device__ __align__(16) __nv_bfloat16 g_wh[WTOT];
__device__ __align__(16) __nv_bfloat16 g_wl[WTOT];
__device__ float g_b12[64];
__device__ int g_deg[N_NODES];
__device__ int g_rowptr[N_NODES + 1];
__device__ int g_cursor[N_NODES];
__device__ int g_csrc[N_EDGES];

// ---------------- helpers ----------------
__device__ __forceinline__ uint32_t smem_to_u32(const void* p) {
    uint32_t a;
    asm("{ .reg .u64 t; cvta.to.shared.u64 t, %1; cvt.u32.u64 %0, t; }" : "=r"(a) : "l"(p));
    return a;
}
__device__ __forceinline__ void ldmatrix_x4(uint32_t* r, uint32_t addr) {
    asm volatile("ldmatrix.sync.aligned.m8n8.x4.shared.b16 {%0,%1,%2,%3}, [%4];"
        : "=r"(r[0]), "=r"(r[1]), "=r"(r[2]), "=r"(r[3]) : "r"(addr));
}
__device__ __forceinline__ void ldmatrix_x2(uint32_t* r, uint32_t addr) {
    asm volatile("ldmatrix.sync.aligned.m8n8.x2.shared.b16 {%0,%1}, [%2];"
        : "=r"(r[0]), "=r"(r[1]) : "r"(addr));
}
__device__ __forceinline__ void mma_bf16(float* c, const uint32_t* a, const uint32_t* b) {
    asm volatile("mma.sync.aligned.m16n8k16.row.col.f32.bf16.bf16.f32 "
        "{%0,%1,%2,%3}, {%4,%5,%6,%7}, {%8,%9}, {%0,%1,%2,%3};"
        : "+f"(c[0]), "+f"(c[1]), "+f"(c[2]), "+f"(c[3])
        : "r"(a[0]), "r"(a[1]), "r"(a[2]), "r"(a[3]), "r"(b[0]), "r"(b[1]));
}
__device__ __forceinline__ uint32_t pack_bf16(float a, float b) {
    __nv_bfloat162 p = __floats2bfloat162_rn(a, b);
    return *reinterpret_cast<uint32_t*>(&p);
}

// ---------------- CSR build (x4 unrolled, MLP=4) + weight pre-conversion ---------------
__global__ void count_deg_convw_kernel(const int* __restrict__ dst,
                                       const float* __restrict__ W0,
                                       const float* __restrict__ W1,
                                       const float* __restrict__ W2) {
    int t = blockIdx.x * blockDim.x + threadIdx.x;
    int e = t * 4;
    if (e + 4 <= N_EDGES) {
        int4 d4 = *(const int4*)(dst + e);
        atomicAdd(&g_deg[d4.x], 1);
        atomicAdd(&g_deg[d4.y], 1);
        atomicAdd(&g_deg[d4.z], 1);
        atomicAdd(&g_deg[d4.w], 1);
    } else {
        for (int i = e; i < N_EDGES; i++) atomicAdd(&g_deg[dst[i]], 1);
    }
    if (t < WOFF_12) {
        float v;
        if      (t < WOFF_1) v = W0[t - WOFF_0];
        else if (t < WOFF_2) v = W1[t - WOFF_1];
        else                 v = W2[t - WOFF_2];
        __nv_bfloat16 hi = __float2bfloat16_rn(v);
        g_wh[t] = hi;
        g_wl[t] = __float2bfloat16_rn(v - __bfloat162float(hi));
    }
}

// single-block chunked exclusive scan; re-zeroes g_deg for the next replay
__global__ void scan_kernel() {
    __shared__ int warp_sums[32];
    __shared__ int sCarry;
    const int tid  = threadIdx.x;       // 1024
    const int lane = tid & 31;
    const int wid  = tid >> 5;
    if (tid == 0) sCarry = 0;
    __syncthreads();
    for (int base = 0; base < N_NODES; base += 1024) {
        int idx = base + tid;
        int v = (idx < N_NODES) ? g_deg[idx] : 0;
        if (idx < N_NODES) g_deg[idx] = 0;
        int incl = v;
        #pragma unroll
        for (int d = 1; d < 32; d <<= 1) {
            int t = __shfl_up_sync(0xffffffffu, incl, d);
            if (lane >= d) incl += t;
        }
        if (lane == 31) warp_sums[wid] = incl;
        __syncthreads();
        if (wid == 0) {
            int s = warp_sums[lane];
            #pragma unroll
            for (int d = 1; d < 32; d <<= 1) {
                int t = __shfl_up_sync(0xffffffffu, s, d);
                if (lane >= d) s += t;
            }
            warp_sums[lane] = s;
        }
        __syncthreads();
        int carry = sCarry;
        int woff  = (wid > 0) ? warp_sums[wid - 1] : 0;
        int excl  = carry + woff + incl - v;
        if (idx < N_NODES) { g_rowptr[idx] = excl; g_cursor[idx] = excl; }
        __syncthreads();
        if (tid == 0) sCarry = carry + warp_sums[31];
        __syncthreads();
    }
    if (tid == 0) g_rowptr[N_NODES] = N_EDGES;
}

__global__ void scatter_kernel(const int* __restrict__ src, const int* __restrict__ dst) {
    int t = blockIdx.x * blockDim.x + threadIdx.x;
    int e = t * 4;
    if (e + 4 <= N_EDGES) {
        int4 d4 = *(const int4*)(dst + e);
        int4 s4 = *(const int4*)(src + e);
        int p0 = atomicAdd(&g_cursor[d4.x], 1);
        int p1 = atomicAdd(&g_cursor[d4.y], 1);
        int p2 = atomicAdd(&g_cursor[d4.z], 1);
        int p3 = atomicAdd(&g_cursor[d4.w], 1);
        g_csrc[p0] = s4.x;
        g_csrc[p1] = s4.y;
        g_csrc[p2] = s4.z;
        g_csrc[p3] = s4.w;
    } else {
        for (int i = e; i < N_EDGES; i++) {
            int pos = atomicAdd(&g_cursor[dst[i]], 1);
            g_csrc[pos] = src[i];
        }
    }
}

// ---------------- head weight fold: W12 = Wp2 @ Wp1 [40,128] padded to 64 ----------------
__global__ void w12_prep_kernel(const float* __restrict__ Wp1, const float* __restrict__ bp1,
                                const float* __restrict__ Wp2, const float* __restrict__ bp2) {
    __shared__ float wp2s[N_CLS * C_DIM];
    const int tid = threadIdx.x;             // 256
    for (int i = tid; i < N_CLS * C_DIM; i += 256) wp2s[i] = Wp2[i];
    __syncthreads();
    for (int idx = tid; idx < 64 * 128; idx += 256) {
        int o = idx >> 7, k = idx & 127;
        float v = 0.f;
        if (o < N_CLS) {
            #pragma unroll 8
            for (int c = 0; c < C_DIM; c++)
                v += wp2s[o * C_DIM + c] * Wp1[c * 128 + k];
        }
        __nv_bfloat16 hi = __float2bfloat16_rn(v);
        g_wh[WOFF_12 + idx] = hi;
        g_wl[WOFF_12 + idx] = __float2bfloat16_rn(v - __bfloat162float(hi));
    }
    if (tid < 64) {
        float b = 0.f;
        if (tid < N_CLS) {
            for (int c = 0; c < C_DIM; c++) b += wp2s[tid * C_DIM + c] * bp1[c];
            b += bp2[tid];
        }
        g_b12[tid] = b;
    }
}

// ---------------- HMMA 2-term GEMM, BM=64 BN=64, warp tile 32x16 -----------------------
// A_FP32: A from fp32 x (convert to bf16-hi in stage). else A = g_hb (bf16).
// MODE 0: PQ epilogue (write half2(P,Q) to g_pq)
// MODE 1: fused head epilogue (logits -> smem -> log_softmax -> out)
template <bool A_FP32, int MODE>
__global__ void __launch_bounds__(256, 4) hmma_gemm2(
    const float* __restrict__ Afp,
    const __nv_bfloat16* __restrict__ whBase, const __nv_bfloat16* __restrict__ wlBase,
    const float* __restrict__ bias, const float* __restrict__ al,
    float* __restrict__ Out)
{
    constexpr int LD = 136;
    constexpr int CW = 16;
    constexpr int NT = 2;
    extern __shared__ char smem[];
    const uint32_t su = smem_to_u32(smem);
    const uint32_t OFF_A  = 0;
    const uint32_t OFF_BH = 64 * LD * 2;
    const uint32_t OFF_BL = OFF_BH + 64 * LD * 2;

    const int tid  = threadIdx.x;
    const int warp = tid >> 5;
    const int lane = tid & 31;
    const int warp_r = warp & 1;
    const int warp_c = warp >> 1;
    const int rowBase = blockIdx.x * 64;
    const int colBase = blockIdx.y * 64;
    const __nv_bfloat16* wh = whBase + (size_t)colBase * 128;
    const __nv_bfloat16* wl = wlBase + (size_t)colBase * 128;

    // ---- stage A ----
    if (A_FP32) {
        #pragma unroll
        for (int it = 0; it < 8; it++) {
            int i = tid + it * 256;           // 64*32 float4 slots
            int r = i >> 5, c = (i & 31) * 4;
            int grow = rowBase + r;
            float4 v = make_float4(0.f, 0.f, 0.f, 0.f);
            if (grow < N_NODES) v = *(const float4*)(Afp + (size_t)grow * 128 + c);
            uint2 hi = make_uint2(pack_bf16(v.x, v.y), pack_bf16(v.z, v.w));
            *(uint2*)(smem + OFF_A + ((size_t)r * LD + c) * 2) = hi;
        }
    } else {
        #pragma unroll
        for (int it = 0; it < 4; it++) {
            int i = tid + it * 256;           // 64*16 uint4 slots
            int r = i >> 4, c = (i & 15) * 8;
            int grow = rowBase + r;
            uint4 v = make_uint4(0u, 0u, 0u, 0u);
            if (grow < N_NODES) v = *(const uint4*)(g_hb + (size_t)grow * 128 + c);
            *(uint4*)(smem + OFF_A + ((size_t)r * LD + c) * 2) = v;
        }
    }
    // ---- stage B ----
    #pragma unroll
    for (int it = 0; it < 4; it++) {
        int i = tid + it * 256;
        int r = i >> 4, c = (i & 15) * 8;
        uint4 vh = *(const uint4*)(wh + (size_t)r * 128 + c);
        uint4 vl = *(const uint4*)(wl + (size_t)r * 128 + c);
        *(uint4*)(smem + OFF_BH + ((size_t)r * LD + c) * 2) = vh;
        *(uint4*)(smem + OFF_BL + ((size_t)r * LD + c) * 2) = vl;
    }
    __syncthreads();

    float acc[2][NT][4];
    #pragma unroll
    for (int s = 0; s < 2; s++)
        #pragma unroll
        for (int n = 0; n < NT; n++)
            #pragma unroll
            for (int j = 0; j < 4; j++) acc[s][n][j] = 0.f;

    uint32_t a_off[2];
    #pragma unroll
    for (int s = 0; s < 2; s++)
        a_off[s] = (uint32_t)(((warp_r * 32 + s * 16 + (lane & 7) + ((lane >> 3) & 1) * 8) * LD
                               + ((lane >> 4) * 8)) * 2);
    const uint32_t b_lane_off =
        (uint32_t)(((warp_c * CW + (lane & 7)) * LD + ((lane >> 3) & 1) * 8) * 2);

    #pragma unroll
    for (int k0 = 0; k0 < 128; k0 += 16) {
        uint32_t a0[4], a1[4];
        ldmatrix_x4(a0, su + OFF_A + a_off[0] + k0 * 2);
        ldmatrix_x4(a1, su + OFF_A + a_off[1] + k0 * 2);
        #pragma unroll
        for (int n = 0; n < NT; n++) {
            uint32_t bh[2], bl[2];
            uint32_t boff = b_lane_off + (uint32_t)(n * 8 * LD * 2) + k0 * 2;
            ldmatrix_x2(bh, su + OFF_BH + boff);
            ldmatrix_x2(bl, su + OFF_BL + boff);
            mma_bf16(acc[0][n], a0, bh);
            mma_bf16(acc[0][n], a0, bl);
            mma_bf16(acc[1][n], a1, bh);
            mma_bf16(acc[1][n], a1, bl);
        }
    }

    if (MODE == 0) {
        #pragma unroll
        for (int s = 0; s < 2; s++) {
            const int r0 = rowBase + warp_r * 32 + s * 16 + (lane >> 2);
            const int r1 = r0 + 8;
            #pragma unroll
            for (int n = 0; n < NT; n++) {
                const int col = colBase + warp_c * CW + n * 8 + (lane & 3) * 2;
                const float bx = bias[col], by = bias[col + 1];
                const float a0 = al[col], a1 = al[col + 1];
                if (r0 < N_NODES) {
                    float h0v = acc[s][n][0] + bx, h1v = acc[s][n][1] + by;
                    float P0 = __expf(a0 * h0v), P1 = __expf(a1 * h1v);
                    __half2 x0 = __floats2half2_rn(P0, P0 * h0v);
                    __half2 x1 = __floats2half2_rn(P1, P1 * h1v);
                    uint2 u; u.x = *(uint32_t*)&x0; u.y = *(uint32_t*)&x1;
                    *(uint2*)(g_pq + (size_t)r0 * 128 + col) = u;
                }
                if (r1 < N_NODES) {
                    float h0v = acc[s][n][2] + bx, h1v = acc[s][n][3] + by;
                    float P0 = __expf(a0 * h0v), P1 = __expf(a1 * h1v);
                    __half2 x0 = __floats2half2_rn(P0, P0 * h0v);
                    __half2 x1 = __floats2half2_rn(P1, P1 * h1v);
                    uint2 u; u.x = *(uint32_t*)&x0; u.y = *(uint32_t*)&x1;
                    *(uint2*)(g_pq + (size_t)r1 * 128 + col) = u;
                }
            }
        }
    } else {
        // ---- fused head epilogue: logits -> smem -> per-row log_softmax -> out ----
        constexpr int LSTRIDE = 68;                 // floats per row (272 B)
        float* lg = (float*)smem;                   // reuse staging smem (64*68*4 = 17408 B)
        __syncthreads();                            // mainloop done reading smem
        #pragma unroll
        for (int s = 0; s < 2; s++) {
            const int rl = warp_r * 32 + s * 16 + (lane >> 2);
            #pragma unroll
            for (int n = 0; n < NT; n++) {
                const int col = warp_c * CW + n * 8 + (lane & 3) * 2;
                const float bx = bias[col], by = bias[col + 1];
                lg[rl * LSTRIDE + col]           = acc[s][n][0] + bx;
                lg[rl * LSTRIDE + col + 1]       = acc[s][n][1] + by;
                lg[(rl + 8) * LSTRIDE + col]     = acc[s][n][2] + bx;
                lg[(rl + 8) * LSTRIDE + col + 1] = acc[s][n][3] + by;
            }
        }
        __syncthreads();
        if (tid < 64) {
            const int node = rowBase + tid;
            if (node < N_NODES) {
                const float* row = lg + tid * LSTRIDE;
                float l[N_CLS];
                #pragma unroll
                for (int j = 0; j < N_CLS; j++) l[j] = row[j];
                float m = l[0];
                #pragma unroll
                for (int j = 1; j < N_CLS; j++) m = fmaxf(m, l[j]);
                float se = 0.f;
                #pragma unroll
                for (int j = 0; j < N_CLS; j++) se += __expf(l[j] - m);
                float lse = m + __logf(se);
                float* orow = Out + (size_t)node * N_CLS;
                #pragma unroll
                for (int j = 0; j < N_CLS; j += 4) {
                    float4 v = make_float4(l[j] - lse, l[j+1] - lse,
                                           l[j+2] - lse, l[j+3] - lse);
                    *(float4*)(orow + j) = v;
                }
            }
        }
    }
}

// ---------------- aggregation: warp/node, gather half2(P,Q), write bf16 h ----------------
__global__ void gat_agg_sum() {
    const int node = blockIdx.x * (blockDim.x >> 5) + (threadIdx.x >> 5);
    if (node >= N_NODES) return;
    const int lane = threadIdx.x & 31;
    const int beg = g_rowptr[node];
    const int end = g_rowptr[node + 1];

    float S0=0.f,S1=0.f,S2=0.f,S3=0.f;
    float A0=0.f,A1=0.f,A2=0.f,A3=0.f;

    const uint4* __restrict__ pq = (const uint4*)g_pq;
    #define ACCUM(v) do { \
        __half2 p0 = *(__half2*)&(v).x, p1 = *(__half2*)&(v).y; \
        __half2 p2 = *(__half2*)&(v).z, p3 = *(__half2*)&(v).w; \
        float2 f0 = __half22float2(p0), f1 = __half22float2(p1); \
        float2 f2 = __half22float2(p2), f3 = __half22float2(p3); \
        S0 += f0.x; A0 += f0.y;  S1 += f1.x; A1 += f1.y; \
        S2 += f2.x; A2 += f2.y;  S3 += f3.x; A3 += f3.y; \
    } while (0)

    int e = beg;
    for (; e + 8 <= end; e += 8) {
        int s0 = __ldg(&g_csrc[e + 0]);
        int s1 = __ldg(&g_csrc[e + 1]);
        int s2 = __ldg(&g_csrc[e + 2]);
        int s3 = __ldg(&g_csrc[e + 3]);
        int s4 = __ldg(&g_csrc[e + 4]);
        int s5 = __ldg(&g_csrc[e + 5]);
        int s6 = __ldg(&g_csrc[e + 6]);
        int s7 = __ldg(&g_csrc[e + 7]);
        uint4 v0 = pq[(size_t)s0 * 32 + lane];
        uint4 v1 = pq[(size_t)s1 * 32 + lane];
        uint4 v2 = pq[(size_t)s2 * 32 + lane];
        uint4 v3 = pq[(size_t)s3 * 32 + lane];
        uint4 v4 = pq[(size_t)s4 * 32 + lane];
        uint4 v5 = pq[(size_t)s5 * 32 + lane];
        uint4 v6 = pq[(size_t)s6 * 32 + lane];
        uint4 v7 = pq[(size_t)s7 * 32 + lane];
        ACCUM(v0); ACCUM(v1); ACCUM(v2); ACCUM(v3);
        ACCUM(v4); ACCUM(v5); ACCUM(v6); ACCUM(v7);
    }
    for (; e + 2 <= end; e += 2) {
        int s0 = __ldg(&g_csrc[e + 0]);
        int s1 = __ldg(&g_csrc[e + 1]);
        uint4 v0 = pq[(size_t)s0 * 32 + lane];
        uint4 v1 = pq[(size_t)s1 * 32 + lane];
        ACCUM(v0); ACCUM(v1);
    }
    for (; e < end; e++) {
        int s = __ldg(&g_csrc[e]);
        uint4 v = pq[(size_t)s * 32 + lane];
        ACCUM(v);
    }
    #undef ACCUM

    float ox = fmaxf(A0 / (S0 + EPS_F), 0.f);
    float oy = fmaxf(A1 / (S1 + EPS_F), 0.f);
    float oz = fmaxf(A2 / (S2 + EPS_F), 0.f);
    float ow = fmaxf(A3 / (S3 + EPS_F), 0.f);
    uint2 u;
    u.x = pack_bf16(ox, oy);
    u.y = pack_bf16(oz, ow);
    *(uint2*)(g_hb + (size_t)node * HCDIM + lane * 4) = u;
}

// ---------------- launch ----------------
extern "C" void kernel_launch(void* const* d_in, const int* in_sizes, int n_in,
                              void* d_out, int out_size) {
    const float* x   = (const float*)d_in[0];
    const int*   ei  = (const int*)  d_in[1];
    const float* W0  = (const float*)d_in[2];
    const float* b0  = (const float*)d_in[3];
    const float* al0 = (const float*)d_in[4];
    const float* W1  = (const float*)d_in[6];
    const float* b1  = (const float*)d_in[7];
    const float* al1 = (const float*)d_in[8];
    const float* W2  = (const float*)d_in[10];
    const float* b2  = (const float*)d_in[11];
    const float* al2 = (const float*)d_in[12];
    const float* Wp1 = (const float*)d_in[14];
    const float* bp1 = (const float*)d_in[15];
    const float* Wp2 = (const float*)d_in[16];
    const float* bp2 = (const float*)d_in[17];
    float* out = (float*)d_out;

    const int* srcv = ei;
    const int* dstv = ei + N_EDGES;

    float *b12;
    __nv_bfloat16 *wh, *wl;
    cudaGetSymbolAddress((void**)&wh, g_wh);
    cudaGetSymbolAddress((void**)&wl, g_wl);
    cudaGetSymbolAddress((void**)&b12, g_b12);

    constexpr int LD = 136;
    const int SMEM2 = (64 * LD + 2 * 64 * LD) * 2;          // 52224
    cudaFuncSetAttribute((const void*)hmma_gemm2<true, 0>,
                         cudaFuncAttributeMaxDynamicSharedMemorySize, SMEM2);
    cudaFuncSetAttribute((const void*)hmma_gemm2<false, 0>,
                         cudaFuncAttributeMaxDynamicSharedMemorySize, SMEM2);
    cudaFuncSetAttribute((const void*)hmma_gemm2<false, 1>,
                         cudaFuncAttributeMaxDynamicSharedMemorySize, SMEM2);

    // CSR + weight conversion (x4-unrolled count/scatter)
    const int e4Grid = (N_EDGES / 4 + 255) / 256;           // 782
    count_deg_convw_kernel<<<e4Grid, 256>>>(dstv, W0, W1, W2);
    scan_kernel<<<1, 1024>>>();
    scatter_kernel<<<e4Grid, 256>>>(srcv, dstv);

    const dim3 g2((N_NODES + 63) / 64, 2);
    const dim3 g1((N_NODES + 63) / 64, 1);
    const int aggGrid = (N_NODES + 7) / 8;

    // layer 0 (launch #4 -> ncu target)
    hmma_gemm2<true, 0><<<g2, 256, SMEM2>>>(x, wh + WOFF_0, wl + WOFF_0, b0, al0, nullptr);
    w12_prep_kernel<<<1, 256>>>(Wp1, bp1, Wp2, bp2);
    gat_agg_sum<<<aggGrid, 256>>>();
    // layer 1
    hmma_gemm2<false, 0><<<g2, 256, SMEM2>>>(nullptr, wh + WOFF_1, wl + WOFF_1, b1, al1, nullptr);
    gat_agg_sum<<<aggGrid, 256>>>();
    // layer 2
    hmma_gemm2<false, 0><<<g2, 256, SMEM2>>>(nullptr, wh + WOFF_2, wl + WOFF_2, b2, al2, nullptr);
    gat_agg_sum<<<aggGrid, 256>>>();
    // head: fused (Wp2@Wp1) GEMM + log_softmax epilogue -> out
    hmma_gemm2<false, 1><<<g1, 256, SMEM2>>>(nullptr, wh + WOFF_12, wl + WOFF_12, b12, nullptr, out);
}